// round 10
// baseline (speedup 1.0000x reference)
#include <cuda_runtime.h>
#include <math.h>

#define BSZ 256
#define LNUM 8

// ---------------- scratch (device globals; no runtime alloc) ----------------
__device__ float g_last[BSZ * 4096];
__device__ float g_d0[BSZ * 4096];
__device__ float g_bypass[LNUM][BSZ * 4096];
__device__ float g_cc[BSZ * 100 * 64];
__device__ float g_q[BSZ * 128 * 64];
__device__ float g_kbuf[BSZ * 128 * 64];
__device__ float g_vw[BSZ * 128 * 8];
__device__ float g_xg[BSZ * 64 * 384];
__device__ float g_fore[BSZ * 4096];
__device__ float g_back[BSZ * 4096];
__device__ float g_mstate[BSZ * 1024];
__device__ float g_states[LNUM * BSZ * 2 * 64];
__device__ float g_sL[2][LNUM][BSZ];
__device__ float g_WqkL[LNUM][2][64 * 192];
__device__ float g_biasqkL[LNUM][2][192];
__device__ float g_constsL[LNUM][6];   // per att: cadd, SP, SN
__device__ float g_WgruL[LNUM][64 * 384];
__device__ float g_gbiasL[LNUM][384];

// zero the p<9 cc slices (atomic accumulation targets)
__device__ __forceinline__ void zero_cc_slices(int idx) {
    int b = idx / (9 * 64);
    int r2 = idx % (9 * 64);
    int p = r2 >> 6, d = r2 & 63;
    g_cc[(b * 100 + p) * 64 + d] = 0.f;
}

// ---------------- prep0: unpack x -> last, mstate; zero cc slices -----------
__global__ void prep0_kernel(const float* __restrict__ x, const float* __restrict__ state) {
    int idx = blockIdx.x * 256 + threadIdx.x;
    if (idx < BSZ * 4096) {
        int b = idx >> 12;
        int r = idx & 4095;
        int j = r >> 6, c = r & 63;
        g_last[idx] = x[b * 5120 + j * 80 + c];
    }
    if (idx < BSZ * 1024) {
        int b = idx >> 10;
        int m = (idx >> 6) & 15;
        int t = idx & 63;
        g_mstate[idx] = state[idx] + x[b * 5120 + t * 80 + 64 + m];
    }
    if (idx < BSZ * 9 * 64) zero_cc_slices(idx);
}

// ---------------- prep-all-layers: combined weights, consts ----------------
__global__ void prep_all_kernel(const float* __restrict__ qkv_w, const float* __restrict__ qkv_b,
                                const float* __restrict__ out_w, const float* __restrict__ out_b,
                                const float* __restrict__ ff_w, const float* __restrict__ gru_k,
                                const float* __restrict__ gru_b) {
    int li = blockIdx.x;
    int role = blockIdx.y;
    int tid = threadIdx.x;
    if (role < 2) {
        int att = role;
        __shared__ float wsum[64];
        __shared__ float red[256];
        if (tid < 64) {
            const float* ow = out_w + (li * 2 + att) * 4096 + tid * 64;
            float s = 0.f;
            for (int d = 0; d < 64; d++) s += ow[d];
            wsum[tid] = s;
        }
        __syncthreads();
        float* W = g_WqkL[li][att];
        float* bia = g_biasqkL[li][att];
        const float* qw = qkv_w + (li * 2 + att) * 3 * 4096;
        for (int idx = tid; idx < 64 * 192; idx += 256) {
            int d = idx / 192, j = idx % 192;
            float v;
            if (j < 64) v = qw[d * 64 + j];
            else if (j < 128) v = qw[4096 + d * 64 + (j - 64)];
            else if (j < 136) {
                int h = j - 128;
                float s = 0.f;
                for (int k = 0; k < 8; k++) s += qw[2 * 4096 + d * 64 + h * 8 + k] * wsum[h * 8 + k];
                v = s;
            } else v = 0.f;
            W[idx] = v;
        }
        if (tid < 192) {
            const float* qb = qkv_b + (li * 2 + att) * 3 * 64;
            float v;
            if (tid < 64) v = qb[tid];
            else if (tid < 128) v = qb[64 + (tid - 64)];
            else if (tid < 136) {
                int h = tid - 128;
                float s = 0.f;
                for (int k = 0; k < 8; k++) s += qb[128 + h * 8 + k] * wsum[h * 8 + k];
                v = s;
            } else v = 0.f;
            bia[tid] = v;
        }
        const float* w0 = ff_w + (li * 2 + att) * 8192;
        float sp = 0.f, sn = 0.f;
        for (int idx = tid; idx < 4096; idx += 256) {
            float w = w0[idx];
            sp += fmaxf(w, 0.f);
            sn += fminf(w, 0.f);
        }
        red[tid] = sp; __syncthreads();
        for (int o = 128; o; o >>= 1) { if (tid < o) red[tid] += red[tid + o]; __syncthreads(); }
        if (tid == 0) g_constsL[li][att * 3 + 1] = red[0];
        __syncthreads();
        red[tid] = sn; __syncthreads();
        for (int o = 128; o; o >>= 1) { if (tid < o) red[tid] += red[tid + o]; __syncthreads(); }
        if (tid == 0) g_constsL[li][att * 3 + 2] = red[0];
        if (tid == 0) {
            float bos = 0.f;
            const float* ob = out_b + (li * 2 + att) * 64;
            for (int d = 0; d < 64; d++) bos += ob[d];
            g_constsL[li][att * 3 + 0] = (att == 0 ? 100.f : 128.f) * bos;
        }
    } else {
        for (int idx = tid; idx < 64 * 384; idx += 256) {
            int d = idx / 384, j = idx % 384;
            int dir = j / 192, g = j % 192;
            g_WgruL[li][idx] = gru_k[(li * 2 + dir) * 12288 + d * 192 + g];
        }
        for (int t = tid; t < 384; t += 256) {
            int dir = t / 192, g = t % 192;
            g_gbiasL[li][t] = gru_b[((li * 2 + dir) * 2 + 0) * 192 + g];
        }
        if (tid < 256) {
            g_sL[0][li][tid] = 0.f;
            g_sL[1][li][tid] = 0.f;
        }
    }
}

// ---------------- conv: full-K staging per tap, few atomics, fused bias -----
__global__ void __launch_bounds__(256) conv_kernel(
        const float* __restrict__ w4, const float* __restrict__ w3,
        const float* __restrict__ w2, const float* __restrict__ w1,
        const float* __restrict__ cb) {
    __shared__ float Ash[64][65];
    __shared__ float Wsh[64][64];
    __shared__ float bsh[64];
    int item = blockIdx.x, bb = blockIdx.y * 64;
    int tid = threadIdx.x;
    int tx = tid & 15, ty = tid >> 4;

    int type, p0, np, split, t0, t1;
    const float* wb;
    if (item < 8)       { type = 3; p0 = 36 + item * 8; np = 8; wb = w1; split = 0; t0 = 0; t1 = 1; }
    else if (item < 35) { type = 2; p0 = 9 + (item - 8); np = 1; wb = w2; split = 0; t0 = 0; t1 = 8; }
    else if (item < 67) {
        int idx = item - 35; type = 1; p0 = 1 + (idx >> 2); np = 1; wb = w3; split = idx & 3;
        t0 = split * 7; t1 = min(27, t0 + 7);
    } else { type = 0; p0 = 0; np = 1; wb = w4; split = item - 67; t0 = split * 8; t1 = t0 + 8; }
    bool direct = (type >= 2);

    if (tid < 64) bsh[tid] = cb[type * 64 + tid];

    for (int pi = 0; pi < np; pi++) {
        int p = p0 + pi;
        int q = (type == 0) ? 0 : (type == 1) ? (p - 1) : (type == 2) ? (p - 9) : (p - 36);
        float acc[4][4] = {};
        for (int tap = t0; tap < t1; tap++) {
            int spat;
            if (type == 0) spat = tap;
            else if (type == 1) {
                int oz = q >> 2, oy = (q >> 1) & 1, ox = q & 1;
                int dz = tap / 9, rem = tap % 9, dy = rem / 3, dx = rem % 3;
                spat = (oz + dz) * 16 + (oy + dy) * 4 + (ox + dx);
            } else if (type == 2) {
                int oz = q / 9, rem2 = q % 9, oy = rem2 / 3, ox = rem2 % 3;
                int dz = tap >> 2, dy = (tap >> 1) & 1, dx = tap & 1;
                spat = (oz + dz) * 16 + (oy + dy) * 4 + (ox + dx);
            } else spat = q;
#pragma unroll
            for (int r = 0; r < 16; r++) {
                int idx = r * 256 + tid;
                int rl = idx >> 6, k = idx & 63;
                Ash[rl][k] = g_last[(bb + rl) * 4096 + spat * 64 + k];
            }
#pragma unroll
            for (int r = 0; r < 16; r++) {
                int idx = r * 256 + tid;
                int k = idx >> 6, d = idx & 63;
                Wsh[k][d] = wb[(tap * 64 + k) * 64 + d];
            }
            __syncthreads();
#pragma unroll
            for (int k = 0; k < 64; k++) {
                float a0 = Ash[ty * 4 + 0][k];
                float a1 = Ash[ty * 4 + 1][k];
                float a2 = Ash[ty * 4 + 2][k];
                float a3 = Ash[ty * 4 + 3][k];
                float4 wv = *(const float4*)&Wsh[k][tx * 4];
                acc[0][0] += a0 * wv.x; acc[0][1] += a0 * wv.y; acc[0][2] += a0 * wv.z; acc[0][3] += a0 * wv.w;
                acc[1][0] += a1 * wv.x; acc[1][1] += a1 * wv.y; acc[1][2] += a1 * wv.z; acc[1][3] += a1 * wv.w;
                acc[2][0] += a2 * wv.x; acc[2][1] += a2 * wv.y; acc[2][2] += a2 * wv.z; acc[2][3] += a2 * wv.w;
                acc[3][0] += a3 * wv.x; acc[3][1] += a3 * wv.y; acc[3][2] += a3 * wv.z; acc[3][3] += a3 * wv.w;
            }
            __syncthreads();
        }
        bool addb = direct || (split == 0);
#pragma unroll
        for (int m = 0; m < 4; m++) {
#pragma unroll
            for (int n = 0; n < 4; n++) {
                int row = bb + ty * 4 + m;
                int col = tx * 4 + n;
                float v = acc[m][n] + (addb ? bsh[col] : 0.f);
                float* ptr = &g_cc[(row * 100 + p) * 64 + col];
                if (direct) *ptr = v;
                else atomicAdd(ptr, v);
            }
        }
    }
}

// ---------------- wide projection GEMM: 64x128 tile, 4x8 microtile ----------
// mode 0: cc -> q+k (+vw) (grid 400 x 1)   mode 1: ap -> q+k (+vw) (grid 512 x 1)
// mode 2: gp(d0^T) -> xg (grid 256 x 3)
__global__ void __launch_bounds__(256) proj_kernel(int mode, int att, int li) {
    __shared__ float Ash[64][64];
    __shared__ float Wsh[32][128];
    __shared__ float bsh[128];
    int row0 = blockIdx.x * 64, colTile = blockIdx.y, col0 = colTile * 128;
    int tid = threadIdx.x;
    const float* W = (mode == 2) ? g_WgruL[li] : g_WqkL[li][att];
    const float* bias = (mode == 2) ? g_gbiasL[li] : g_biasqkL[li][att];
    int Wwidth = (mode == 2) ? 384 : 192;

    // stage A once: Ash[rl][k]
    if (mode == 0) {
#pragma unroll
        for (int r = 0; r < 16; r++) {
            int idx = r * 256 + tid;
            int rl = idx >> 6, k = idx & 63;
            Ash[rl][k] = g_cc[(row0 + rl) * 64 + k];
        }
    } else if (mode == 1) {
        int b = row0 >> 7;
        const float* src = ((row0 >> 6) & 1) ? g_back : g_fore;
#pragma unroll
        for (int r = 0; r < 16; r++) {
            int idx = r * 256 + tid;
            int k = idx >> 6, rl = idx & 63;
            Ash[rl][k] = src[(b * 64 + k) * 64 + rl];
        }
    } else {
        int b = row0 >> 6;
#pragma unroll
        for (int r = 0; r < 16; r++) {
            int idx = r * 256 + tid;
            int k = idx >> 6, rl = idx & 63;
            Ash[rl][k] = g_d0[b * 4096 + k * 64 + rl];
        }
    }
    if (tid < 128) bsh[tid] = bias[col0 + tid];

    int tx = tid & 15, ty = tid >> 4;   // tx: 8-col group, ty: 4-row group
    float acc[4][8] = {};
    for (int ks = 0; ks < 2; ks++) {
        // stage W chunk: Wsh[32][128]
#pragma unroll
        for (int r = 0; r < 16; r++) {
            int idx = r * 256 + tid;
            int k = idx >> 7, c = idx & 127;
            Wsh[k][c] = W[(ks * 32 + k) * Wwidth + col0 + c];
        }
        __syncthreads();
#pragma unroll 8
        for (int k = 0; k < 32; k++) {
            int kk = ks * 32 + k;
            float a0 = Ash[ty * 4 + 0][kk];
            float a1 = Ash[ty * 4 + 1][kk];
            float a2 = Ash[ty * 4 + 2][kk];
            float a3 = Ash[ty * 4 + 3][kk];
            float4 w0 = *(const float4*)&Wsh[k][tx * 8];
            float4 w1 = *(const float4*)&Wsh[k][tx * 8 + 4];
            acc[0][0] += a0 * w0.x; acc[0][1] += a0 * w0.y; acc[0][2] += a0 * w0.z; acc[0][3] += a0 * w0.w;
            acc[0][4] += a0 * w1.x; acc[0][5] += a0 * w1.y; acc[0][6] += a0 * w1.z; acc[0][7] += a0 * w1.w;
            acc[1][0] += a1 * w0.x; acc[1][1] += a1 * w0.y; acc[1][2] += a1 * w0.z; acc[1][3] += a1 * w0.w;
            acc[1][4] += a1 * w1.x; acc[1][5] += a1 * w1.y; acc[1][6] += a1 * w1.z; acc[1][7] += a1 * w1.w;
            acc[2][0] += a2 * w0.x; acc[2][1] += a2 * w0.y; acc[2][2] += a2 * w0.z; acc[2][3] += a2 * w0.w;
            acc[2][4] += a2 * w1.x; acc[2][5] += a2 * w1.y; acc[2][6] += a2 * w1.z; acc[2][7] += a2 * w1.w;
            acc[3][0] += a3 * w0.x; acc[3][1] += a3 * w0.y; acc[3][2] += a3 * w0.z; acc[3][3] += a3 * w0.w;
            acc[3][4] += a3 * w1.x; acc[3][5] += a3 * w1.y; acc[3][6] += a3 * w1.z; acc[3][7] += a3 * w1.w;
        }
        __syncthreads();
    }
    // write out (two float4 per row per thread)
#pragma unroll
    for (int m = 0; m < 4; m++) {
        int row = row0 + ty * 4 + m;
        float v[8];
#pragma unroll
        for (int n = 0; n < 8; n++) v[n] = acc[m][n] + bsh[tx * 8 + n];
        if (mode == 2) {
            float* dst = &g_xg[row * 384 + col0 + tx * 8];
            *(float4*)&dst[0] = make_float4(v[0], v[1], v[2], v[3]);
            *(float4*)&dst[4] = make_float4(v[4], v[5], v[6], v[7]);
        } else {
            int b, s;
            if (mode == 0) { b = row / 100; s = row % 100; }
            else { b = row >> 7; s = row & 127; }
            // cols 0..63 -> q, 64..127 -> k; an 8-col group never straddles 64
            float* dst = (tx < 8) ? &g_q[(b * 128 + s) * 64 + tx * 8]
                                  : &g_kbuf[(b * 128 + s) * 64 + (tx - 8) * 8];
            *(float4*)&dst[0] = make_float4(v[0], v[1], v[2], v[3]);
            *(float4*)&dst[4] = make_float4(v[4], v[5], v[6], v[7]);
        }
    }
    // slim vw tile (mode < 2 only): columns 128..135
    if (mode < 2) {
#pragma unroll
        for (int r = 0; r < 2; r++) {
            int idx = r * 256 + tid;
            int k = idx >> 3, c = idx & 7;
            Wsh[0][k * 8 + c] = W[k * Wwidth + 128 + c];   // flat use of Wsh area (4096 floats fits)
        }
        if (tid < 8) bsh[tid] = bias[128 + tid];
        __syncthreads();
        int rl = tid >> 2, quad = tid & 3;
        float a0 = 0.f, a1 = 0.f;
#pragma unroll
        for (int k = 0; k < 64; k++) {
            float a = Ash[rl][k];
            a0 += a * Wsh[0][k * 8 + quad * 2];
            a1 += a * Wsh[0][k * 8 + quad * 2 + 1];
        }
        int row = row0 + rl;
        int b, s;
        if (mode == 0) { b = row / 100; s = row % 100; }
        else { b = row >> 7; s = row & 127; }
        g_vw[(b * 128 + s) * 8 + quad * 2] = a0 + bsh[quad * 2];
        g_vw[(b * 128 + s) * 8 + quad * 2 + 1] = a1 + bsh[quad * 2 + 1];
    }
}

// ---------------- attention -> per-batch scalar (two-pass, unroll x2) -------
__global__ void attn_kernel(int att, int S, int li) {
    __shared__ float ksh[128][8];
    __shared__ float qsh[128][8];
    __shared__ float vwsh[128];
    __shared__ float part[4];
    int b = blockIdx.x, h = blockIdx.y;
    int tid = threadIdx.x;
    for (int idx = tid; idx < S * 8; idx += 128) {
        int s = idx >> 3, kk = idx & 7;
        ksh[s][kk] = g_kbuf[(b * 128 + s) * 64 + h * 8 + kk];
        qsh[s][kk] = g_q[(b * 128 + s) * 64 + h * 8 + kk] * 0.35355339059327373f;
    }
    for (int idx = tid; idx < S; idx += 128)
        vwsh[idx] = g_vw[(b * 128 + idx) * 8 + h];
    __syncthreads();
    float contrib = 0.f;
    if (tid < S) {
        float qv[8];
#pragma unroll
        for (int kk = 0; kk < 8; kk++) qv[kk] = qsh[tid][kk];
        float m = -1e30f;
        for (int s = 0; s < S; s += 2) {
            float z0 = 0.f, z1 = 0.f;
#pragma unroll
            for (int kk = 0; kk < 8; kk++) {
                z0 += qv[kk] * ksh[s][kk];
                z1 += qv[kk] * ksh[s + 1][kk];
            }
            m = fmaxf(m, fmaxf(z0, z1));
        }
        float l = 0.f, acc = 0.f;
        for (int s = 0; s < S; s += 2) {
            float z0 = 0.f, z1 = 0.f;
#pragma unroll
            for (int kk = 0; kk < 8; kk++) {
                z0 += qv[kk] * ksh[s][kk];
                z1 += qv[kk] * ksh[s + 1][kk];
            }
            float e0 = __expf(z0 - m);
            float e1 = __expf(z1 - m);
            l += e0 + e1;
            acc += e0 * vwsh[s] + e1 * vwsh[s + 1];
        }
        contrib = acc / l;
    }
    for (int o = 16; o; o >>= 1) contrib += __shfl_xor_sync(0xffffffffu, contrib, o);
    if ((tid & 31) == 0) part[tid >> 5] = contrib;
    __syncthreads();
    if (tid == 0) {
        float t = part[0] + part[1] + part[2] + part[3];
        atomicAdd(&g_sL[att][li][b], t);
    }
}

// row reduction over 64 elems spread across 2 warps (4 rows per 256-thr block)
__device__ __forceinline__ float rowsum64(float v, float* part, int warp, int lane, int rl) {
#pragma unroll
    for (int o = 16; o; o >>= 1) v += __shfl_xor_sync(0xffffffffu, v, o);
    if (lane == 0) part[warp] = v;
    __syncthreads();
    float s = part[rl * 2] + part[rl * 2 + 1];
    __syncthreads();
    return s;
}

// ---------------- LN0: d0 = LN(ff + last) ----------------
__global__ void lnd0_kernel(int li, const float* __restrict__ ffw1,
                            const float* __restrict__ ang, const float* __restrict__ anb) {
    __shared__ float part[8];
    int tid = threadIdx.x;
    int b = blockIdx.x;
    int rl = tid >> 6;
    int j = blockIdx.y * 4 + rl;
    int c = tid & 63;
    int warp = tid >> 5, lane = tid & 31;
    const float* cst = g_constsL[li];
    float s = g_sL[0][li][b] + cst[0];
    float t = s * (s > 0.f ? cst[1] : cst[2]);
    int idx = (b * 64 + j) * 64 + c;
    float v = t * ffw1[j * 64 + c] + g_last[idx];
    float mean = rowsum64(v, part, warp, lane, rl) * (1.f / 64.f);
    float d = v - mean;
    float var = rowsum64(d * d, part, warp, lane, rl) * (1.f / 64.f);
    g_d0[idx] = d * rsqrtf(var + 1e-3f) * ang[c] + anb[c];
}

// ---------------- final LN + fused skip-LN chain (+ rolling cc zero) --------
__global__ void lnfinal_kernel(int li, int nstages, const float* __restrict__ ffw1,
                               const float* __restrict__ ang, const float* __restrict__ anb,
                               const float* __restrict__ sg, const float* __restrict__ sb) {
    __shared__ float part[8];
    int tid = threadIdx.x;
    int b = blockIdx.x;
    int rl = tid >> 6;
    int j = blockIdx.y * 4 + rl;
    int c = tid & 63;
    int warp = tid >> 5, lane = tid & 31;
    if (li < LNUM - 1) {
        int lb = blockIdx.y * BSZ + b;
        int zidx = lb * 256 + tid;
        if (zidx < BSZ * 9 * 64) zero_cc_slices(zidx);
    }
    const float* cst = g_constsL[li];
    float s = g_sL[1][li][b] + cst[3];
    float t = s * (s > 0.f ? cst[4] : cst[5]);
    int idx = (b * 64 + j) * 64 + c;
    float v = t * ffw1[j * 64 + c] + g_d0[idx];
    {
        float mean = rowsum64(v, part, warp, lane, rl) * (1.f / 64.f);
        float d = v - mean;
        float var = rowsum64(d * d, part, warp, lane, rl) * (1.f / 64.f);
        v = d * rsqrtf(var + 1e-3f) * ang[c] + anb[c];
    }
    g_bypass[li][idx] = v;
    float cur = v;
    for (int st = 0; st < nstages; st++) {
        int bidx = li - (1 << st) + 1;
        float u = (bidx == li) ? v : g_bypass[bidx][idx];
        float w = u + cur;
        float mean = rowsum64(w, part, warp, lane, rl) * (1.f / 64.f);
        float d = w - mean;
        float var = rowsum64(d * d, part, warp, lane, rl) * (1.f / 64.f);
        cur = d * rsqrtf(var + 1e-3f) * sg[st * 64 + c] + sb[st * 64 + c];
    }
    g_last[idx] = cur;
}

// ---------------- GRU: one block per (batch, dir), xg prefetch --------------
__global__ void __launch_bounds__(192) gru_kernel(const float* __restrict__ gru_r,
                                                  const float* __restrict__ gru_b, int li) {
    int b = blockIdx.x, dir = blockIdx.y;
    int g = threadIdx.x;
    float rcol[64];
    const float* rp = gru_r + (li * 2 + dir) * 12288;
#pragma unroll
    for (int j = 0; j < 64; j++) rcol[j] = rp[j * 192 + g];
    float br = gru_b[((li * 2 + dir) * 2 + 1) * 192 + g];
    __shared__ float hsh[64];
    __shared__ float hgsh[192];
    __shared__ float xgsh[192];
    if (g < 64) hsh[g] = g_mstate[b * 1024 + (li * 2 + dir) * 64 + g];
    __syncthreads();
    float* outp = dir ? g_back : g_fore;
    const float* xgbase = &g_xg[b * 64 * 384 + dir * 192 + g];
    float xgv_next = xgbase[(dir ? 63 : 0) * 384];
    for (int t = 0; t < 64; t++) {
        float xgv = xgv_next;
        if (t < 63) {
            int trow_n = dir ? (62 - t) : (t + 1);
            xgv_next = xgbase[trow_n * 384];
        }
        float a0 = 0.f, a1 = 0.f, a2 = 0.f, a3 = 0.f;
#pragma unroll
        for (int j = 0; j < 64; j += 4) {
            a0 += hsh[j]     * rcol[j];
            a1 += hsh[j + 1] * rcol[j + 1];
            a2 += hsh[j + 2] * rcol[j + 2];
            a3 += hsh[j + 3] * rcol[j + 3];
        }
        hgsh[g] = br + ((a0 + a1) + (a2 + a3));
        xgsh[g] = xgv;
        __syncthreads();
        if (g < 64) {
            float z = 1.f / (1.f + __expf(-(xgsh[g] + hgsh[g])));
            float rt = 1.f / (1.f + __expf(-(xgsh[64 + g] + hgsh[64 + g])));
            float cgate = tanhf(xgsh[128 + g] + rt * hgsh[128 + g]);
            float hn = z * hsh[g] + (1.f - z) * cgate;
            hsh[g] = hn;
            outp[(b * 64 + t) * 64 + g] = hn;
        }
        __syncthreads();
    }
    if (g < 64) g_states[((li * BSZ + b) * 2 + dir) * 64 + g] = hsh[g];
}

// ---------------- assemble outputs ----------------
__global__ void assemble_kernel(float* __restrict__ out) {
    int idx = blockIdx.x * 256 + threadIdx.x;
    const int N1 = BSZ * 5120;
    if (idx < N1) {
        int b = idx / 5120;
        int r = idx % 5120;
        int j = r / 80, c = r % 80;
        float v;
        if (c < 64) v = g_last[b * 4096 + j * 64 + c];
        else {
            int m = c - 64;
            int l = m >> 1, dir = m & 1;
            v = g_states[((l * BSZ + b) * 2 + dir) * 64 + j];
        }
        out[idx] = v;
    } else if (idx < N1 + BSZ * 1024) {
        int idx2 = idx - N1;
        int b = idx2 >> 10;
        int m = (idx2 >> 6) & 15;
        int t = idx2 & 63;
        int l = m >> 1, dir = m & 1;
        out[idx] = g_states[((l * BSZ + b) * 2 + dir) * 64 + t];
    }
}

// ---------------- host ----------------
extern "C" void kernel_launch(void* const* d_in, const int* in_sizes, int n_in,
                              void* d_out, int out_size) {
    const float* x       = (const float*)d_in[0];
    const float* state   = (const float*)d_in[1];
    const float* conv_w4 = (const float*)d_in[2];
    const float* conv_w3 = (const float*)d_in[3];
    const float* conv_w2 = (const float*)d_in[4];
    const float* conv_w1 = (const float*)d_in[5];
    const float* conv_b  = (const float*)d_in[6];
    const float* qkv_w   = (const float*)d_in[7];
    const float* qkv_b   = (const float*)d_in[8];
    const float* out_w   = (const float*)d_in[9];
    const float* out_b   = (const float*)d_in[10];
    const float* ff_w    = (const float*)d_in[11];
    const float* an_g    = (const float*)d_in[12];
    const float* an_b    = (const float*)d_in[13];
    const float* gru_k   = (const float*)d_in[14];
    const float* gru_r   = (const float*)d_in[15];
    const float* gru_b   = (const float*)d_in[16];
    const float* skip_g  = (const float*)d_in[17];
    const float* skip_b  = (const float*)d_in[18];
    float* out = (float*)d_out;

    prep0_kernel<<<4096, 256>>>(x, state);
    prep_all_kernel<<<dim3(8, 3), 256>>>(qkv_w, qkv_b, out_w, out_b, ff_w, gru_k, gru_b);

    for (int i = 0; i < LNUM; i++) {
        conv_kernel<<<dim3(75, 4), 256>>>(conv_w4 + i * 262144, conv_w3 + i * 110592,
                                          conv_w2 + i * 32768, conv_w1 + i * 4096,
                                          conv_b + i * 256);
        proj_kernel<<<dim3(400, 1), 256>>>(0, 0, i);
        attn_kernel<<<dim3(BSZ, 8), 128>>>(0, 100, i);
        lnd0_kernel<<<dim3(BSZ, 16), 256>>>(i, ff_w + (i * 2 + 0) * 8192 + 4096,
                                            an_g + (i * 2 + 0) * 64, an_b + (i * 2 + 0) * 64);
        proj_kernel<<<dim3(256, 3), 256>>>(2, 0, i);
        gru_kernel<<<dim3(BSZ, 2), 192>>>(gru_r, gru_b, i);
        proj_kernel<<<dim3(512, 1), 256>>>(1, 1, i);
        attn_kernel<<<dim3(BSZ, 8), 128>>>(1, 128, i);
        int nst = 1;
        { int jj = 2; while ((i + 1) % jj == 0 && nst < 4) { nst++; jj *= 2; } }
        lnfinal_kernel<<<dim3(BSZ, 16), 256>>>(i, nst, ff_w + (i * 2 + 1) * 8192 + 4096,
                                               an_g + (i * 2 + 1) * 64, an_b + (i * 2 + 1) * 64,
                                               skip_g + i * 4 * 64, skip_b + i * 4 * 64);
    }
    assemble_kernel<<<6144, 256>>>(out);
}

// round 11
// speedup vs baseline: 1.1616x; 1.1616x over previous
#include <cuda_runtime.h>
#include <math.h>

#define BSZ 256
#define LNUM 8

// ---------------- scratch (device globals; no runtime alloc) ----------------
__device__ float g_last[BSZ * 4096];
__device__ float g_d0[BSZ * 4096];
__device__ float g_bypass[LNUM][BSZ * 4096];
__device__ float g_cc[BSZ * 100 * 64];
__device__ float g_q[BSZ * 128 * 64];
__device__ float g_kbuf[BSZ * 128 * 64];
__device__ float g_vw[BSZ * 128 * 8];
__device__ float g_xg[BSZ * 64 * 384];
__device__ float g_fore[BSZ * 4096];
__device__ float g_back[BSZ * 4096];
__device__ float g_mstate[BSZ * 1024];
__device__ float g_states[LNUM * BSZ * 2 * 64];
__device__ float g_sL[2][LNUM][BSZ];
__device__ float g_WqkL[LNUM][2][64 * 192];
__device__ float g_biasqkL[LNUM][2][192];
__device__ float g_constsL[LNUM][6];   // per att: cadd, SP, SN
__device__ float g_WgruL[LNUM][64 * 384];
__device__ float g_gbiasL[LNUM][384];

// zero the p<9 cc slices (atomic accumulation targets)
__device__ __forceinline__ void zero_cc_slices(int idx) {
    int b = idx / (9 * 64);
    int r2 = idx % (9 * 64);
    int p = r2 >> 6, d = r2 & 63;
    g_cc[(b * 100 + p) * 64 + d] = 0.f;
}

// ---------------- prep0: unpack x -> last, mstate; zero cc slices -----------
__global__ void prep0_kernel(const float* __restrict__ x, const float* __restrict__ state) {
    int idx = blockIdx.x * 256 + threadIdx.x;
    if (idx < BSZ * 4096) {
        int b = idx >> 12;
        int r = idx & 4095;
        int j = r >> 6, c = r & 63;
        g_last[idx] = x[b * 5120 + j * 80 + c];
    }
    if (idx < BSZ * 1024) {
        int b = idx >> 10;
        int m = (idx >> 6) & 15;
        int t = idx & 63;
        g_mstate[idx] = state[idx] + x[b * 5120 + t * 80 + 64 + m];
    }
    if (idx < BSZ * 9 * 64) zero_cc_slices(idx);
}

// ---------------- prep-all-layers: combined weights, consts ----------------
__global__ void prep_all_kernel(const float* __restrict__ qkv_w, const float* __restrict__ qkv_b,
                                const float* __restrict__ out_w, const float* __restrict__ out_b,
                                const float* __restrict__ ff_w, const float* __restrict__ gru_k,
                                const float* __restrict__ gru_b) {
    int li = blockIdx.x;
    int role = blockIdx.y;
    int tid = threadIdx.x;
    if (role < 2) {
        int att = role;
        __shared__ float wsum[64];
        __shared__ float red[256];
        if (tid < 64) {
            const float* ow = out_w + (li * 2 + att) * 4096 + tid * 64;
            float s = 0.f;
            for (int d = 0; d < 64; d++) s += ow[d];
            wsum[tid] = s;
        }
        __syncthreads();
        float* W = g_WqkL[li][att];
        float* bia = g_biasqkL[li][att];
        const float* qw = qkv_w + (li * 2 + att) * 3 * 4096;
        for (int idx = tid; idx < 64 * 192; idx += 256) {
            int d = idx / 192, j = idx % 192;
            float v;
            if (j < 64) v = qw[d * 64 + j];
            else if (j < 128) v = qw[4096 + d * 64 + (j - 64)];
            else if (j < 136) {
                int h = j - 128;
                float s = 0.f;
                for (int k = 0; k < 8; k++) s += qw[2 * 4096 + d * 64 + h * 8 + k] * wsum[h * 8 + k];
                v = s;
            } else v = 0.f;
            W[idx] = v;
        }
        if (tid < 192) {
            const float* qb = qkv_b + (li * 2 + att) * 3 * 64;
            float v;
            if (tid < 64) v = qb[tid];
            else if (tid < 128) v = qb[64 + (tid - 64)];
            else if (tid < 136) {
                int h = tid - 128;
                float s = 0.f;
                for (int k = 0; k < 8; k++) s += qb[128 + h * 8 + k] * wsum[h * 8 + k];
                v = s;
            } else v = 0.f;
            bia[tid] = v;
        }
        const float* w0 = ff_w + (li * 2 + att) * 8192;
        float sp = 0.f, sn = 0.f;
        for (int idx = tid; idx < 4096; idx += 256) {
            float w = w0[idx];
            sp += fmaxf(w, 0.f);
            sn += fminf(w, 0.f);
        }
        red[tid] = sp; __syncthreads();
        for (int o = 128; o; o >>= 1) { if (tid < o) red[tid] += red[tid + o]; __syncthreads(); }
        if (tid == 0) g_constsL[li][att * 3 + 1] = red[0];
        __syncthreads();
        red[tid] = sn; __syncthreads();
        for (int o = 128; o; o >>= 1) { if (tid < o) red[tid] += red[tid + o]; __syncthreads(); }
        if (tid == 0) g_constsL[li][att * 3 + 2] = red[0];
        if (tid == 0) {
            float bos = 0.f;
            const float* ob = out_b + (li * 2 + att) * 64;
            for (int d = 0; d < 64; d++) bos += ob[d];
            g_constsL[li][att * 3 + 0] = (att == 0 ? 100.f : 128.f) * bos;
        }
    } else {
        for (int idx = tid; idx < 64 * 384; idx += 256) {
            int d = idx / 384, j = idx % 384;
            int dir = j / 192, g = j % 192;
            g_WgruL[li][idx] = gru_k[(li * 2 + dir) * 12288 + d * 192 + g];
        }
        for (int t = tid; t < 384; t += 256) {
            int dir = t / 192, g = t % 192;
            g_gbiasL[li][t] = gru_b[((li * 2 + dir) * 2 + 0) * 192 + g];
        }
        if (tid < 256) {
            g_sL[0][li][tid] = 0.f;
            g_sL[1][li][tid] = 0.f;
        }
    }
}

// ---------------- conv: full-K staging per tap, few atomics, fused bias -----
__global__ void __launch_bounds__(256) conv_kernel(
        const float* __restrict__ w4, const float* __restrict__ w3,
        const float* __restrict__ w2, const float* __restrict__ w1,
        const float* __restrict__ cb) {
    __shared__ float Ash[64][65];
    __shared__ float Wsh[64][64];
    __shared__ float bsh[64];
    int item = blockIdx.x, bb = blockIdx.y * 64;
    int tid = threadIdx.x;
    int tx = tid & 15, ty = tid >> 4;

    int type, p0, np, split, t0, t1;
    const float* wb;
    if (item < 8)       { type = 3; p0 = 36 + item * 8; np = 8; wb = w1; split = 0; t0 = 0; t1 = 1; }
    else if (item < 35) { type = 2; p0 = 9 + (item - 8); np = 1; wb = w2; split = 0; t0 = 0; t1 = 8; }
    else if (item < 67) {
        int idx = item - 35; type = 1; p0 = 1 + (idx >> 2); np = 1; wb = w3; split = idx & 3;
        t0 = split * 7; t1 = min(27, t0 + 7);
    } else { type = 0; p0 = 0; np = 1; wb = w4; split = item - 67; t0 = split * 8; t1 = t0 + 8; }
    bool direct = (type >= 2);

    if (tid < 64) bsh[tid] = cb[type * 64 + tid];

    for (int pi = 0; pi < np; pi++) {
        int p = p0 + pi;
        int q = (type == 0) ? 0 : (type == 1) ? (p - 1) : (type == 2) ? (p - 9) : (p - 36);
        float acc[4][4] = {};
        for (int tap = t0; tap < t1; tap++) {
            int spat;
            if (type == 0) spat = tap;
            else if (type == 1) {
                int oz = q >> 2, oy = (q >> 1) & 1, ox = q & 1;
                int dz = tap / 9, rem = tap % 9, dy = rem / 3, dx = rem % 3;
                spat = (oz + dz) * 16 + (oy + dy) * 4 + (ox + dx);
            } else if (type == 2) {
                int oz = q / 9, rem2 = q % 9, oy = rem2 / 3, ox = rem2 % 3;
                int dz = tap >> 2, dy = (tap >> 1) & 1, dx = tap & 1;
                spat = (oz + dz) * 16 + (oy + dy) * 4 + (ox + dx);
            } else spat = q;
#pragma unroll
            for (int r = 0; r < 16; r++) {
                int idx = r * 256 + tid;
                int rl = idx >> 6, k = idx & 63;
                Ash[rl][k] = g_last[(bb + rl) * 4096 + spat * 64 + k];
            }
#pragma unroll
            for (int r = 0; r < 16; r++) {
                int idx = r * 256 + tid;
                int k = idx >> 6, d = idx & 63;
                Wsh[k][d] = wb[(tap * 64 + k) * 64 + d];
            }
            __syncthreads();
#pragma unroll
            for (int k = 0; k < 64; k++) {
                float a0 = Ash[ty * 4 + 0][k];
                float a1 = Ash[ty * 4 + 1][k];
                float a2 = Ash[ty * 4 + 2][k];
                float a3 = Ash[ty * 4 + 3][k];
                float4 wv = *(const float4*)&Wsh[k][tx * 4];
                acc[0][0] += a0 * wv.x; acc[0][1] += a0 * wv.y; acc[0][2] += a0 * wv.z; acc[0][3] += a0 * wv.w;
                acc[1][0] += a1 * wv.x; acc[1][1] += a1 * wv.y; acc[1][2] += a1 * wv.z; acc[1][3] += a1 * wv.w;
                acc[2][0] += a2 * wv.x; acc[2][1] += a2 * wv.y; acc[2][2] += a2 * wv.z; acc[2][3] += a2 * wv.w;
                acc[3][0] += a3 * wv.x; acc[3][1] += a3 * wv.y; acc[3][2] += a3 * wv.z; acc[3][3] += a3 * wv.w;
            }
            __syncthreads();
        }
        bool addb = direct || (split == 0);
#pragma unroll
        for (int m = 0; m < 4; m++) {
#pragma unroll
            for (int n = 0; n < 4; n++) {
                int row = bb + ty * 4 + m;
                int col = tx * 4 + n;
                float v = acc[m][n] + (addb ? bsh[col] : 0.f);
                float* ptr = &g_cc[(row * 100 + p) * 64 + col];
                if (direct) *ptr = v;
                else atomicAdd(ptr, v);
            }
        }
    }
}

// ---------------- projection GEMM (col-split) --------------------------------
// mode 0: cc -> q/k/vw (grid 400 x 3)   mode 1: ap -> q/k/vw (grid 512 x 3)
// mode 2: gp(LN(ff+last)^T) -> xg, fused LN, colTile 0 writes d0 (grid 256 x 6)
__global__ void __launch_bounds__(256) proj_kernel(int mode, int att, int li,
        const float* __restrict__ ffw1, const float* __restrict__ ang,
        const float* __restrict__ anb) {
    __shared__ float Ash[64][65];
    __shared__ float Wsh[64][64];
    __shared__ float bsh[64];
    __shared__ float pls[4][64];
    __shared__ float angs[64], anbs[64];
    int row0 = blockIdx.x * 64, colTile = blockIdx.y, col0 = colTile * 64;
    int tid = threadIdx.x;
    const float* W = (mode == 2) ? g_WgruL[li] : g_WqkL[li][att];
    const float* bias = (mode == 2) ? g_gbiasL[li] : g_biasqkL[li][att];
    int Wwidth = (mode == 2) ? 384 : 192;
    bool slim = (mode < 2 && colTile == 2);

    if (mode == 0) {
#pragma unroll
        for (int r = 0; r < 16; r++) {
            int idx = r * 256 + tid;
            int rl = idx >> 6, k = idx & 63;
            Ash[rl][k] = g_cc[(row0 + rl) * 64 + k];
        }
    } else if (mode == 1) {
        int b = row0 >> 7;
        const float* src = ((row0 >> 6) & 1) ? g_back : g_fore;
#pragma unroll
        for (int r = 0; r < 16; r++) {
            int idx = r * 256 + tid;
            int k = idx >> 6, rl = idx & 63;
            Ash[rl][k] = src[(b * 64 + k) * 64 + rl];
        }
    } else {
        // fused LN: Ash[c][j] = LN_c( t*ffw1[j,c] + last[b,j,c] )
        int b = row0 >> 6;
        const float* cst = g_constsL[li];
        float sv = g_sL[0][li][b] + cst[0];
        float tmul = sv * (sv > 0.f ? cst[1] : cst[2]);
        if (tid < 64) { angs[tid] = ang[tid]; anbs[tid] = anb[tid]; }
#pragma unroll
        for (int r = 0; r < 16; r++) {
            int idx = r * 256 + tid;
            int j = idx >> 6, c = idx & 63;
            Ash[c][j] = tmul * ffw1[idx] + g_last[b * 4096 + idx];
        }
        __syncthreads();
        int col = tid & 63, sub = tid >> 6;
        float ps = 0.f;
#pragma unroll
        for (int i2 = 0; i2 < 16; i2++) ps += Ash[sub * 16 + i2][col];
        pls[sub][col] = ps;
        __syncthreads();
        float mean = (pls[0][col] + pls[1][col] + pls[2][col] + pls[3][col]) * (1.f / 64.f);
        float vs = 0.f;
#pragma unroll
        for (int i2 = 0; i2 < 16; i2++) {
            float d = Ash[sub * 16 + i2][col] - mean;
            vs += d * d;
        }
        __syncthreads();
        pls[sub][col] = vs;
        __syncthreads();
        float var = (pls[0][col] + pls[1][col] + pls[2][col] + pls[3][col]) * (1.f / 64.f);
        float inv = rsqrtf(var + 1e-3f);
#pragma unroll
        for (int i2 = 0; i2 < 16; i2++) {
            int c = sub * 16 + i2;
            Ash[c][col] = (Ash[c][col] - mean) * inv * angs[c] + anbs[c];
        }
        __syncthreads();
        if (colTile == 0) {
#pragma unroll
            for (int r = 0; r < 16; r++) {
                int idx = r * 256 + tid;
                int j = idx >> 6, c = idx & 63;
                g_d0[b * 4096 + idx] = Ash[c][j];
            }
        }
    }

    if (!slim) {
#pragma unroll
        for (int r = 0; r < 16; r++) {
            int idx = r * 256 + tid;
            int k = idx >> 6, c = idx & 63;
            Wsh[k][c] = W[k * Wwidth + col0 + c];
        }
        if (tid < 64) bsh[tid] = bias[col0 + tid];
        __syncthreads();
        int tx = tid & 15, ty = tid >> 4;
        float acc[4][4] = {};
#pragma unroll
        for (int k = 0; k < 64; k++) {
            float a0 = Ash[ty * 4 + 0][k];
            float a1 = Ash[ty * 4 + 1][k];
            float a2 = Ash[ty * 4 + 2][k];
            float a3 = Ash[ty * 4 + 3][k];
            float4 wv = *(const float4*)&Wsh[k][tx * 4];
            acc[0][0] += a0 * wv.x; acc[0][1] += a0 * wv.y; acc[0][2] += a0 * wv.z; acc[0][3] += a0 * wv.w;
            acc[1][0] += a1 * wv.x; acc[1][1] += a1 * wv.y; acc[1][2] += a1 * wv.z; acc[1][3] += a1 * wv.w;
            acc[2][0] += a2 * wv.x; acc[2][1] += a2 * wv.y; acc[2][2] += a2 * wv.z; acc[2][3] += a2 * wv.w;
            acc[3][0] += a3 * wv.x; acc[3][1] += a3 * wv.y; acc[3][2] += a3 * wv.z; acc[3][3] += a3 * wv.w;
        }
#pragma unroll
        for (int m = 0; m < 4; m++) {
#pragma unroll
            for (int n = 0; n < 4; n++) {
                int row = row0 + ty * 4 + m;
                int col = tx * 4 + n;
                float v = acc[m][n] + bsh[col];
                if (mode == 2) {
                    g_xg[row * 384 + col0 + col] = v;
                } else {
                    int b, s;
                    if (mode == 0) { b = row / 100; s = row % 100; }
                    else { b = row >> 7; s = row & 127; }
                    float* dst = (colTile == 0) ? g_q : g_kbuf;
                    dst[(b * 128 + s) * 64 + col] = v;
                }
            }
        }
    } else {
#pragma unroll
        for (int r = 0; r < 2; r++) {
            int idx = r * 256 + tid;
            int k = idx >> 3, c = idx & 7;
            Wsh[k][c] = W[k * Wwidth + 128 + c];
        }
        if (tid < 8) bsh[tid] = bias[128 + tid];
        __syncthreads();
        int rl = tid >> 2, quad = tid & 3;
        float a0 = 0.f, a1 = 0.f;
#pragma unroll
        for (int k = 0; k < 64; k++) {
            float a = Ash[rl][k];
            a0 += a * Wsh[k][quad * 2];
            a1 += a * Wsh[k][quad * 2 + 1];
        }
        int row = row0 + rl;
        int b, s;
        if (mode == 0) { b = row / 100; s = row % 100; }
        else { b = row >> 7; s = row & 127; }
        g_vw[(b * 128 + s) * 8 + quad * 2] = a0 + bsh[quad * 2];
        g_vw[(b * 128 + s) * 8 + quad * 2 + 1] = a1 + bsh[quad * 2 + 1];
    }
}

// ---------------- attention -> per-batch scalar (two-pass, unroll x2) -------
__global__ void attn_kernel(int att, int S, int li) {
    __shared__ float ksh[128][8];
    __shared__ float qsh[128][8];
    __shared__ float vwsh[128];
    __shared__ float part[4];
    int b = blockIdx.x, h = blockIdx.y;
    int tid = threadIdx.x;
    for (int idx = tid; idx < S * 8; idx += 128) {
        int s = idx >> 3, kk = idx & 7;
        ksh[s][kk] = g_kbuf[(b * 128 + s) * 64 + h * 8 + kk];
        qsh[s][kk] = g_q[(b * 128 + s) * 64 + h * 8 + kk] * 0.35355339059327373f;
    }
    for (int idx = tid; idx < S; idx += 128)
        vwsh[idx] = g_vw[(b * 128 + idx) * 8 + h];
    __syncthreads();
    float contrib = 0.f;
    if (tid < S) {
        float qv[8];
#pragma unroll
        for (int kk = 0; kk < 8; kk++) qv[kk] = qsh[tid][kk];
        float m = -1e30f;
        for (int s = 0; s < S; s += 2) {
            float z0 = 0.f, z1 = 0.f;
#pragma unroll
            for (int kk = 0; kk < 8; kk++) {
                z0 += qv[kk] * ksh[s][kk];
                z1 += qv[kk] * ksh[s + 1][kk];
            }
            m = fmaxf(m, fmaxf(z0, z1));
        }
        float l = 0.f, acc = 0.f;
        for (int s = 0; s < S; s += 2) {
            float z0 = 0.f, z1 = 0.f;
#pragma unroll
            for (int kk = 0; kk < 8; kk++) {
                z0 += qv[kk] * ksh[s][kk];
                z1 += qv[kk] * ksh[s + 1][kk];
            }
            float e0 = __expf(z0 - m);
            float e1 = __expf(z1 - m);
            l += e0 + e1;
            acc += e0 * vwsh[s] + e1 * vwsh[s + 1];
        }
        contrib = acc / l;
    }
    for (int o = 16; o; o >>= 1) contrib += __shfl_xor_sync(0xffffffffu, contrib, o);
    if ((tid & 31) == 0) part[tid >> 5] = contrib;
    __syncthreads();
    if (tid == 0) {
        float t = part[0] + part[1] + part[2] + part[3];
        atomicAdd(&g_sL[att][li][b], t);
    }
}

// row reduction over 64 elems spread across 2 warps (4 rows per 256-thr block)
__device__ __forceinline__ float rowsum64(float v, float* part, int warp, int lane, int rl) {
#pragma unroll
    for (int o = 16; o; o >>= 1) v += __shfl_xor_sync(0xffffffffu, v, o);
    if (lane == 0) part[warp] = v;
    __syncthreads();
    float s = part[rl * 2] + part[rl * 2 + 1];
    __syncthreads();
    return s;
}

// ---------------- final LN + fused skip-LN chain (+ rolling cc zero) --------
__global__ void lnfinal_kernel(int li, int nstages, const float* __restrict__ ffw1,
                               const float* __restrict__ ang, const float* __restrict__ anb,
                               const float* __restrict__ sg, const float* __restrict__ sb) {
    __shared__ float part[8];
    int tid = threadIdx.x;
    int b = blockIdx.x;
    int rl = tid >> 6;
    int j = blockIdx.y * 4 + rl;
    int c = tid & 63;
    int warp = tid >> 5, lane = tid & 31;
    if (li < LNUM - 1) {
        int lb = blockIdx.y * BSZ + b;
        int zidx = lb * 256 + tid;
        if (zidx < BSZ * 9 * 64) zero_cc_slices(zidx);
    }
    const float* cst = g_constsL[li];
    float s = g_sL[1][li][b] + cst[3];
    float t = s * (s > 0.f ? cst[4] : cst[5]);
    int idx = (b * 64 + j) * 64 + c;
    float v = t * ffw1[j * 64 + c] + g_d0[idx];
    {
        float mean = rowsum64(v, part, warp, lane, rl) * (1.f / 64.f);
        float d = v - mean;
        float var = rowsum64(d * d, part, warp, lane, rl) * (1.f / 64.f);
        v = d * rsqrtf(var + 1e-3f) * ang[c] + anb[c];
    }
    g_bypass[li][idx] = v;
    float cur = v;
    for (int st = 0; st < nstages; st++) {
        int bidx = li - (1 << st) + 1;
        float u = (bidx == li) ? v : g_bypass[bidx][idx];
        float w = u + cur;
        float mean = rowsum64(w, part, warp, lane, rl) * (1.f / 64.f);
        float d = w - mean;
        float var = rowsum64(d * d, part, warp, lane, rl) * (1.f / 64.f);
        cur = d * rsqrtf(var + 1e-3f) * sg[st * 64 + c] + sb[st * 64 + c];
    }
    g_last[idx] = cur;
}

// ---------------- GRU: one block per (batch, dir), xg prefetch --------------
__global__ void __launch_bounds__(192) gru_kernel(const float* __restrict__ gru_r,
                                                  const float* __restrict__ gru_b, int li) {
    int b = blockIdx.x, dir = blockIdx.y;
    int g = threadIdx.x;
    float rcol[64];
    const float* rp = gru_r + (li * 2 + dir) * 12288;
#pragma unroll
    for (int j = 0; j < 64; j++) rcol[j] = rp[j * 192 + g];
    float br = gru_b[((li * 2 + dir) * 2 + 1) * 192 + g];
    __shared__ float hsh[64];
    __shared__ float hgsh[192];
    __shared__ float xgsh[192];
    if (g < 64) hsh[g] = g_mstate[b * 1024 + (li * 2 + dir) * 64 + g];
    __syncthreads();
    float* outp = dir ? g_back : g_fore;
    const float* xgbase = &g_xg[b * 64 * 384 + dir * 192 + g];
    float xgv_next = xgbase[(dir ? 63 : 0) * 384];
    for (int t = 0; t < 64; t++) {
        float xgv = xgv_next;
        if (t < 63) {
            int trow_n = dir ? (62 - t) : (t + 1);
            xgv_next = xgbase[trow_n * 384];
        }
        float a0 = 0.f, a1 = 0.f, a2 = 0.f, a3 = 0.f;
#pragma unroll
        for (int j = 0; j < 64; j += 4) {
            a0 += hsh[j]     * rcol[j];
            a1 += hsh[j + 1] * rcol[j + 1];
            a2 += hsh[j + 2] * rcol[j + 2];
            a3 += hsh[j + 3] * rcol[j + 3];
        }
        hgsh[g] = br + ((a0 + a1) + (a2 + a3));
        xgsh[g] = xgv;
        __syncthreads();
        if (g < 64) {
            float z = 1.f / (1.f + __expf(-(xgsh[g] + hgsh[g])));
            float rt = 1.f / (1.f + __expf(-(xgsh[64 + g] + hgsh[64 + g])));
            float cgate = tanhf(xgsh[128 + g] + rt * hgsh[128 + g]);
            float hn = z * hsh[g] + (1.f - z) * cgate;
            hsh[g] = hn;
            outp[(b * 64 + t) * 64 + g] = hn;
        }
        __syncthreads();
    }
    if (g < 64) g_states[((li * BSZ + b) * 2 + dir) * 64 + g] = hsh[g];
}

// ---------------- assemble outputs ----------------
__global__ void assemble_kernel(float* __restrict__ out) {
    int idx = blockIdx.x * 256 + threadIdx.x;
    const int N1 = BSZ * 5120;
    if (idx < N1) {
        int b = idx / 5120;
        int r = idx % 5120;
        int j = r / 80, c = r % 80;
        float v;
        if (c < 64) v = g_last[b * 4096 + j * 64 + c];
        else {
            int m = c - 64;
            int l = m >> 1, dir = m & 1;
            v = g_states[((l * BSZ + b) * 2 + dir) * 64 + j];
        }
        out[idx] = v;
    } else if (idx < N1 + BSZ * 1024) {
        int idx2 = idx - N1;
        int b = idx2 >> 10;
        int m = (idx2 >> 6) & 15;
        int t = idx2 & 63;
        int l = m >> 1, dir = m & 1;
        out[idx] = g_states[((l * BSZ + b) * 2 + dir) * 64 + t];
    }
}

// ---------------- host ----------------
extern "C" void kernel_launch(void* const* d_in, const int* in_sizes, int n_in,
                              void* d_out, int out_size) {
    const float* x       = (const float*)d_in[0];
    const float* state   = (const float*)d_in[1];
    const float* conv_w4 = (const float*)d_in[2];
    const float* conv_w3 = (const float*)d_in[3];
    const float* conv_w2 = (const float*)d_in[4];
    const float* conv_w1 = (const float*)d_in[5];
    const float* conv_b  = (const float*)d_in[6];
    const float* qkv_w   = (const float*)d_in[7];
    const float* qkv_b   = (const float*)d_in[8];
    const float* out_w   = (const float*)d_in[9];
    const float* out_b   = (const float*)d_in[10];
    const float* ff_w    = (const float*)d_in[11];
    const float* an_g    = (const float*)d_in[12];
    const float* an_b    = (const float*)d_in[13];
    const float* gru_k   = (const float*)d_in[14];
    const float* gru_r   = (const float*)d_in[15];
    const float* gru_b   = (const float*)d_in[16];
    const float* skip_g  = (const float*)d_in[17];
    const float* skip_b  = (const float*)d_in[18];
    float* out = (float*)d_out;

    prep0_kernel<<<4096, 256>>>(x, state);
    prep_all_kernel<<<dim3(8, 3), 256>>>(qkv_w, qkv_b, out_w, out_b, ff_w, gru_k, gru_b);

    for (int i = 0; i < LNUM; i++) {
        conv_kernel<<<dim3(75, 4), 256>>>(conv_w4 + i * 262144, conv_w3 + i * 110592,
                                          conv_w2 + i * 32768, conv_w1 + i * 4096,
                                          conv_b + i * 256);
        proj_kernel<<<dim3(400, 3), 256>>>(0, 0, i, nullptr, nullptr, nullptr);
        attn_kernel<<<dim3(BSZ, 8), 128>>>(0, 100, i);
        proj_kernel<<<dim3(256, 6), 256>>>(2, 0, i,
                                           ff_w + (i * 2 + 0) * 8192 + 4096,
                                           an_g + (i * 2 + 0) * 64,
                                           an_b + (i * 2 + 0) * 64);
        gru_kernel<<<dim3(BSZ, 2), 192>>>(gru_r, gru_b, i);
        proj_kernel<<<dim3(512, 3), 256>>>(1, 1, i, nullptr, nullptr, nullptr);
        attn_kernel<<<dim3(BSZ, 8), 128>>>(1, 128, i);
        int nst = 1;
        { int jj = 2; while ((i + 1) % jj == 0 && nst < 4) { nst++; jj *= 2; } }
        lnfinal_kernel<<<dim3(BSZ, 16), 256>>>(i, nst, ff_w + (i * 2 + 1) * 8192 + 4096,
                                               an_g + (i * 2 + 1) * 64, an_b + (i * 2 + 1) * 64,
                                               skip_g + i * 4 * 64, skip_b + i * 4 * 64);
    }
    assemble_kernel<<<6144, 256>>>(out);
}

// round 12
// speedup vs baseline: 1.2320x; 1.0605x over previous
#include <cuda_runtime.h>
#include <math.h>

#define BSZ 256
#define LNUM 8

// ---------------- scratch (device globals; no runtime alloc) ----------------
__device__ float g_last[BSZ * 4096];
__device__ float g_d0[BSZ * 4096];
__device__ float g_bypass[LNUM][BSZ * 4096];
__device__ float g_cc[BSZ * 100 * 64];
__device__ float g_q[BSZ * 128 * 64];
__device__ float g_kbuf[BSZ * 128 * 64];
__device__ float g_vw[BSZ * 128 * 8];
__device__ float g_xg[BSZ * 64 * 384];
__device__ float g_fore[BSZ * 4096];
__device__ float g_back[BSZ * 4096];
__device__ float g_mstate[BSZ * 1024];
__device__ float g_states[LNUM * BSZ * 2 * 64];
__device__ float g_sL[2][LNUM][BSZ];
__device__ float g_WqkL[LNUM][2][64 * 192];
__device__ float g_biasqkL[LNUM][2][192];
__device__ float g_constsL[LNUM][6];   // per att: cadd, SP, SN
__device__ float g_WgruL[LNUM][64 * 384];
__device__ float g_gbiasL[LNUM][384];

// zero the p<9 cc slices (atomic accumulation targets)
__device__ __forceinline__ void zero_cc_slices(int idx) {
    int b = idx / (9 * 64);
    int r2 = idx % (9 * 64);
    int p = r2 >> 6, d = r2 & 63;
    g_cc[(b * 100 + p) * 64 + d] = 0.f;
}

// ---------------- prep0: unpack x -> last, mstate; zero cc slices -----------
__global__ void prep0_kernel(const float* __restrict__ x, const float* __restrict__ state) {
    int idx = blockIdx.x * 256 + threadIdx.x;
    if (idx < BSZ * 4096) {
        int b = idx >> 12;
        int r = idx & 4095;
        int j = r >> 6, c = r & 63;
        g_last[idx] = x[b * 5120 + j * 80 + c];
    }
    if (idx < BSZ * 1024) {
        int b = idx >> 10;
        int m = (idx >> 6) & 15;
        int t = idx & 63;
        g_mstate[idx] = state[idx] + x[b * 5120 + t * 80 + 64 + m];
    }
    if (idx < BSZ * 9 * 64) zero_cc_slices(idx);
}

// ---------------- prep-all-layers: combined weights, consts ----------------
__global__ void prep_all_kernel(const float* __restrict__ qkv_w, const float* __restrict__ qkv_b,
                                const float* __restrict__ out_w, const float* __restrict__ out_b,
                                const float* __restrict__ ff_w, const float* __restrict__ gru_k,
                                const float* __restrict__ gru_b) {
    int li = blockIdx.x;
    int role = blockIdx.y;
    int tid = threadIdx.x;
    if (role < 2) {
        int att = role;
        __shared__ float wsum[64];
        __shared__ float red[256];
        if (tid < 64) {
            const float* ow = out_w + (li * 2 + att) * 4096 + tid * 64;
            float s = 0.f;
            for (int d = 0; d < 64; d++) s += ow[d];
            wsum[tid] = s;
        }
        __syncthreads();
        float* W = g_WqkL[li][att];
        float* bia = g_biasqkL[li][att];
        const float* qw = qkv_w + (li * 2 + att) * 3 * 4096;
        for (int idx = tid; idx < 64 * 192; idx += 256) {
            int d = idx / 192, j = idx % 192;
            float v;
            if (j < 64) v = qw[d * 64 + j];
            else if (j < 128) v = qw[4096 + d * 64 + (j - 64)];
            else if (j < 136) {
                int h = j - 128;
                float s = 0.f;
                for (int k = 0; k < 8; k++) s += qw[2 * 4096 + d * 64 + h * 8 + k] * wsum[h * 8 + k];
                v = s;
            } else v = 0.f;
            W[idx] = v;
        }
        if (tid < 192) {
            const float* qb = qkv_b + (li * 2 + att) * 3 * 64;
            float v;
            if (tid < 64) v = qb[tid];
            else if (tid < 128) v = qb[64 + (tid - 64)];
            else if (tid < 136) {
                int h = tid - 128;
                float s = 0.f;
                for (int k = 0; k < 8; k++) s += qb[128 + h * 8 + k] * wsum[h * 8 + k];
                v = s;
            } else v = 0.f;
            bia[tid] = v;
        }
        const float* w0 = ff_w + (li * 2 + att) * 8192;
        float sp = 0.f, sn = 0.f;
        for (int idx = tid; idx < 4096; idx += 256) {
            float w = w0[idx];
            sp += fmaxf(w, 0.f);
            sn += fminf(w, 0.f);
        }
        red[tid] = sp; __syncthreads();
        for (int o = 128; o; o >>= 1) { if (tid < o) red[tid] += red[tid + o]; __syncthreads(); }
        if (tid == 0) g_constsL[li][att * 3 + 1] = red[0];
        __syncthreads();
        red[tid] = sn; __syncthreads();
        for (int o = 128; o; o >>= 1) { if (tid < o) red[tid] += red[tid + o]; __syncthreads(); }
        if (tid == 0) g_constsL[li][att * 3 + 2] = red[0];
        if (tid == 0) {
            float bos = 0.f;
            const float* ob = out_b + (li * 2 + att) * 64;
            for (int d = 0; d < 64; d++) bos += ob[d];
            g_constsL[li][att * 3 + 0] = (att == 0 ? 100.f : 128.f) * bos;
        }
    } else {
        for (int idx = tid; idx < 64 * 384; idx += 256) {
            int d = idx / 384, j = idx % 384;
            int dir = j / 192, g = j % 192;
            g_WgruL[li][idx] = gru_k[(li * 2 + dir) * 12288 + d * 192 + g];
        }
        for (int t = tid; t < 384; t += 256) {
            int dir = t / 192, g = t % 192;
            g_gbiasL[li][t] = gru_b[((li * 2 + dir) * 2 + 0) * 192 + g];
        }
        if (tid < 256) {
            g_sL[0][li][tid] = 0.f;
            g_sL[1][li][tid] = 0.f;
        }
    }
}

// ---------------- conv: vectorized staging, few atomics, fused bias ---------
__global__ void __launch_bounds__(256) conv_kernel(
        const float* __restrict__ w4, const float* __restrict__ w3,
        const float* __restrict__ w2, const float* __restrict__ w1,
        const float* __restrict__ cb) {
    __shared__ float Ash[64][65];
    __shared__ __align__(16) float Wsh[64][64];
    __shared__ float bsh[64];
    int item = blockIdx.x, bb = blockIdx.y * 64;
    int tid = threadIdx.x;
    int tx = tid & 15, ty = tid >> 4;

    int type, p0, np, split, t0, t1;
    const float* wb;
    if (item < 8)       { type = 3; p0 = 36 + item * 8; np = 8; wb = w1; split = 0; t0 = 0; t1 = 1; }
    else if (item < 35) { type = 2; p0 = 9 + (item - 8); np = 1; wb = w2; split = 0; t0 = 0; t1 = 8; }
    else if (item < 67) {
        int idx = item - 35; type = 1; p0 = 1 + (idx >> 2); np = 1; wb = w3; split = idx & 3;
        t0 = split * 7; t1 = min(27, t0 + 7);
    } else { type = 0; p0 = 0; np = 1; wb = w4; split = item - 67; t0 = split * 8; t1 = t0 + 8; }
    bool direct = (type >= 2);

    if (tid < 64) bsh[tid] = cb[type * 64 + tid];

    for (int pi = 0; pi < np; pi++) {
        int p = p0 + pi;
        int q = (type == 0) ? 0 : (type == 1) ? (p - 1) : (type == 2) ? (p - 9) : (p - 36);
        float acc[4][4] = {};
        for (int tap = t0; tap < t1; tap++) {
            int spat;
            if (type == 0) spat = tap;
            else if (type == 1) {
                int oz = q >> 2, oy = (q >> 1) & 1, ox = q & 1;
                int dz = tap / 9, rem = tap % 9, dy = rem / 3, dx = rem % 3;
                spat = (oz + dz) * 16 + (oy + dy) * 4 + (ox + dx);
            } else if (type == 2) {
                int oz = q / 9, rem2 = q % 9, oy = rem2 / 3, ox = rem2 % 3;
                int dz = tap >> 2, dy = (tap >> 1) & 1, dx = tap & 1;
                spat = (oz + dz) * 16 + (oy + dy) * 4 + (ox + dx);
            } else spat = q;
#pragma unroll
            for (int r = 0; r < 4; r++) {
                int idx = r * 256 + tid;
                int rl = idx >> 4, k4 = (idx & 15) * 4;
                float4 av = *(const float4*)&g_last[(bb + rl) * 4096 + spat * 64 + k4];
                Ash[rl][k4]     = av.x;
                Ash[rl][k4 + 1] = av.y;
                Ash[rl][k4 + 2] = av.z;
                Ash[rl][k4 + 3] = av.w;
            }
#pragma unroll
            for (int r = 0; r < 4; r++) {
                int idx = r * 256 + tid;
                int k = idx >> 4, d4 = (idx & 15) * 4;
                float4 wv = *(const float4*)&wb[(tap * 64 + k) * 64 + d4];
                *(float4*)&Wsh[k][d4] = wv;
            }
            __syncthreads();
#pragma unroll
            for (int k = 0; k < 64; k++) {
                float a0 = Ash[ty * 4 + 0][k];
                float a1 = Ash[ty * 4 + 1][k];
                float a2 = Ash[ty * 4 + 2][k];
                float a3 = Ash[ty * 4 + 3][k];
                float4 wv = *(const float4*)&Wsh[k][tx * 4];
                acc[0][0] += a0 * wv.x; acc[0][1] += a0 * wv.y; acc[0][2] += a0 * wv.z; acc[0][3] += a0 * wv.w;
                acc[1][0] += a1 * wv.x; acc[1][1] += a1 * wv.y; acc[1][2] += a1 * wv.z; acc[1][3] += a1 * wv.w;
                acc[2][0] += a2 * wv.x; acc[2][1] += a2 * wv.y; acc[2][2] += a2 * wv.z; acc[2][3] += a2 * wv.w;
                acc[3][0] += a3 * wv.x; acc[3][1] += a3 * wv.y; acc[3][2] += a3 * wv.z; acc[3][3] += a3 * wv.w;
            }
            __syncthreads();
        }
        bool addb = direct || (split == 0);
#pragma unroll
        for (int m = 0; m < 4; m++) {
            int row = bb + ty * 4 + m;
            if (direct) {
                float4 v;
                v.x = acc[m][0] + bsh[tx * 4 + 0];
                v.y = acc[m][1] + bsh[tx * 4 + 1];
                v.z = acc[m][2] + bsh[tx * 4 + 2];
                v.w = acc[m][3] + bsh[tx * 4 + 3];
                *(float4*)&g_cc[(row * 100 + p) * 64 + tx * 4] = v;
            } else {
#pragma unroll
                for (int n = 0; n < 4; n++) {
                    int col = tx * 4 + n;
                    float v = acc[m][n] + (addb ? bsh[col] : 0.f);
                    atomicAdd(&g_cc[(row * 100 + p) * 64 + col], v);
                }
            }
        }
    }
}

// ---------------- projection GEMM (col-split, vectorized staging) -----------
// mode 0: cc -> q/k/vw (grid 400 x 3)   mode 1: ap -> q/k/vw (grid 512 x 3)
// mode 2: gp(LN(ff+last)^T) -> xg, fused LN, colTile 0 writes d0 (grid 256 x 6)
__global__ void __launch_bounds__(256) proj_kernel(int mode, int att, int li,
        const float* __restrict__ ffw1, const float* __restrict__ ang,
        const float* __restrict__ anb) {
    __shared__ float Ash[64][65];
    __shared__ __align__(16) float Wsh[64][64];
    __shared__ float bsh[64];
    __shared__ float pls[4][64];
    __shared__ float angs[64], anbs[64];
    int row0 = blockIdx.x * 64, colTile = blockIdx.y, col0 = colTile * 64;
    int tid = threadIdx.x;
    const float* W = (mode == 2) ? g_WgruL[li] : g_WqkL[li][att];
    const float* bias = (mode == 2) ? g_gbiasL[li] : g_biasqkL[li][att];
    int Wwidth = (mode == 2) ? 384 : 192;
    bool slim = (mode < 2 && colTile == 2);

    if (mode == 0) {
#pragma unroll
        for (int r = 0; r < 4; r++) {
            int idx = r * 256 + tid;
            int rl = idx >> 4, k4 = (idx & 15) * 4;
            float4 av = *(const float4*)&g_cc[(row0 + rl) * 64 + k4];
            Ash[rl][k4]     = av.x;
            Ash[rl][k4 + 1] = av.y;
            Ash[rl][k4 + 2] = av.z;
            Ash[rl][k4 + 3] = av.w;
        }
    } else if (mode == 1) {
        int b = row0 >> 7;
        const float* src = ((row0 >> 6) & 1) ? g_back : g_fore;
#pragma unroll
        for (int r = 0; r < 16; r++) {
            int idx = r * 256 + tid;
            int k = idx >> 6, rl = idx & 63;
            Ash[rl][k] = src[(b * 64 + k) * 64 + rl];
        }
    } else {
        // fused LN: Ash[c][j] = LN_c( t*ffw1[j,c] + last[b,j,c] )
        int b = row0 >> 6;
        const float* cst = g_constsL[li];
        float sv = g_sL[0][li][b] + cst[0];
        float tmul = sv * (sv > 0.f ? cst[1] : cst[2]);
        if (tid < 64) { angs[tid] = ang[tid]; anbs[tid] = anb[tid]; }
#pragma unroll
        for (int r = 0; r < 16; r++) {
            int idx = r * 256 + tid;
            int j = idx >> 6, c = idx & 63;
            Ash[c][j] = tmul * ffw1[idx] + g_last[b * 4096 + idx];
        }
        __syncthreads();
        int col = tid & 63, sub = tid >> 6;
        float ps = 0.f;
#pragma unroll
        for (int i2 = 0; i2 < 16; i2++) ps += Ash[sub * 16 + i2][col];
        pls[sub][col] = ps;
        __syncthreads();
        float mean = (pls[0][col] + pls[1][col] + pls[2][col] + pls[3][col]) * (1.f / 64.f);
        float vs = 0.f;
#pragma unroll
        for (int i2 = 0; i2 < 16; i2++) {
            float d = Ash[sub * 16 + i2][col] - mean;
            vs += d * d;
        }
        __syncthreads();
        pls[sub][col] = vs;
        __syncthreads();
        float var = (pls[0][col] + pls[1][col] + pls[2][col] + pls[3][col]) * (1.f / 64.f);
        float inv = rsqrtf(var + 1e-3f);
#pragma unroll
        for (int i2 = 0; i2 < 16; i2++) {
            int c = sub * 16 + i2;
            Ash[c][col] = (Ash[c][col] - mean) * inv * angs[c] + anbs[c];
        }
        __syncthreads();
        if (colTile == 0) {
#pragma unroll
            for (int r = 0; r < 16; r++) {
                int idx = r * 256 + tid;
                int j = idx >> 6, c = idx & 63;
                g_d0[b * 4096 + idx] = Ash[c][j];
            }
        }
    }

    if (!slim) {
#pragma unroll
        for (int r = 0; r < 4; r++) {
            int idx = r * 256 + tid;
            int k = idx >> 4, c4 = (idx & 15) * 4;
            float4 wv = *(const float4*)&W[k * Wwidth + col0 + c4];
            *(float4*)&Wsh[k][c4] = wv;
        }
        if (tid < 64) bsh[tid] = bias[col0 + tid];
        __syncthreads();
        int tx = tid & 15, ty = tid >> 4;
        float acc[4][4] = {};
#pragma unroll
        for (int k = 0; k < 64; k++) {
            float a0 = Ash[ty * 4 + 0][k];
            float a1 = Ash[ty * 4 + 1][k];
            float a2 = Ash[ty * 4 + 2][k];
            float a3 = Ash[ty * 4 + 3][k];
            float4 wv = *(const float4*)&Wsh[k][tx * 4];
            acc[0][0] += a0 * wv.x; acc[0][1] += a0 * wv.y; acc[0][2] += a0 * wv.z; acc[0][3] += a0 * wv.w;
            acc[1][0] += a1 * wv.x; acc[1][1] += a1 * wv.y; acc[1][2] += a1 * wv.z; acc[1][3] += a1 * wv.w;
            acc[2][0] += a2 * wv.x; acc[2][1] += a2 * wv.y; acc[2][2] += a2 * wv.z; acc[2][3] += a2 * wv.w;
            acc[3][0] += a3 * wv.x; acc[3][1] += a3 * wv.y; acc[3][2] += a3 * wv.z; acc[3][3] += a3 * wv.w;
        }
#pragma unroll
        for (int m = 0; m < 4; m++) {
            int row = row0 + ty * 4 + m;
            float4 v;
            v.x = acc[m][0] + bsh[tx * 4 + 0];
            v.y = acc[m][1] + bsh[tx * 4 + 1];
            v.z = acc[m][2] + bsh[tx * 4 + 2];
            v.w = acc[m][3] + bsh[tx * 4 + 3];
            if (mode == 2) {
                *(float4*)&g_xg[row * 384 + col0 + tx * 4] = v;
            } else {
                int b, s;
                if (mode == 0) { b = row / 100; s = row % 100; }
                else { b = row >> 7; s = row & 127; }
                float* dst = (colTile == 0) ? g_q : g_kbuf;
                *(float4*)&dst[(b * 128 + s) * 64 + tx * 4] = v;
            }
        }
    } else {
#pragma unroll
        for (int r = 0; r < 2; r++) {
            int idx = r * 256 + tid;
            int k = idx >> 3, c = idx & 7;
            Wsh[k][c] = W[k * Wwidth + 128 + c];
        }
        if (tid < 8) bsh[tid] = bias[128 + tid];
        __syncthreads();
        int rl = tid >> 2, quad = tid & 3;
        float a0 = 0.f, a1 = 0.f;
#pragma unroll
        for (int k = 0; k < 64; k++) {
            float a = Ash[rl][k];
            a0 += a * Wsh[k][quad * 2];
            a1 += a * Wsh[k][quad * 2 + 1];
        }
        int row = row0 + rl;
        int b, s;
        if (mode == 0) { b = row / 100; s = row % 100; }
        else { b = row >> 7; s = row & 127; }
        g_vw[(b * 128 + s) * 8 + quad * 2] = a0 + bsh[quad * 2];
        g_vw[(b * 128 + s) * 8 + quad * 2 + 1] = a1 + bsh[quad * 2 + 1];
    }
}

// ---------------- attention -> per-batch scalar (two-pass, unroll x2) -------
__global__ void attn_kernel(int att, int S, int li) {
    __shared__ float ksh[128][8];
    __shared__ float qsh[128][8];
    __shared__ float vwsh[128];
    __shared__ float part[4];
    int b = blockIdx.x, h = blockIdx.y;
    int tid = threadIdx.x;
    for (int idx = tid; idx < S * 8; idx += 128) {
        int s = idx >> 3, kk = idx & 7;
        ksh[s][kk] = g_kbuf[(b * 128 + s) * 64 + h * 8 + kk];
        qsh[s][kk] = g_q[(b * 128 + s) * 64 + h * 8 + kk] * 0.35355339059327373f;
    }
    for (int idx = tid; idx < S; idx += 128)
        vwsh[idx] = g_vw[(b * 128 + idx) * 8 + h];
    __syncthreads();
    float contrib = 0.f;
    if (tid < S) {
        float qv[8];
#pragma unroll
        for (int kk = 0; kk < 8; kk++) qv[kk] = qsh[tid][kk];
        float m = -1e30f;
        for (int s = 0; s < S; s += 2) {
            float z0 = 0.f, z1 = 0.f;
#pragma unroll
            for (int kk = 0; kk < 8; kk++) {
                z0 += qv[kk] * ksh[s][kk];
                z1 += qv[kk] * ksh[s + 1][kk];
            }
            m = fmaxf(m, fmaxf(z0, z1));
        }
        float l = 0.f, acc = 0.f;
        for (int s = 0; s < S; s += 2) {
            float z0 = 0.f, z1 = 0.f;
#pragma unroll
            for (int kk = 0; kk < 8; kk++) {
                z0 += qv[kk] * ksh[s][kk];
                z1 += qv[kk] * ksh[s + 1][kk];
            }
            float e0 = __expf(z0 - m);
            float e1 = __expf(z1 - m);
            l += e0 + e1;
            acc += e0 * vwsh[s] + e1 * vwsh[s + 1];
        }
        contrib = acc / l;
    }
    for (int o = 16; o; o >>= 1) contrib += __shfl_xor_sync(0xffffffffu, contrib, o);
    if ((tid & 31) == 0) part[tid >> 5] = contrib;
    __syncthreads();
    if (tid == 0) {
        float t = part[0] + part[1] + part[2] + part[3];
        atomicAdd(&g_sL[att][li][b], t);
    }
}

// row reduction over 64 elems spread across 2 warps (4 rows per 256-thr block)
__device__ __forceinline__ float rowsum64(float v, float* part, int warp, int lane, int rl) {
#pragma unroll
    for (int o = 16; o; o >>= 1) v += __shfl_xor_sync(0xffffffffu, v, o);
    if (lane == 0) part[warp] = v;
    __syncthreads();
    float s = part[rl * 2] + part[rl * 2 + 1];
    __syncthreads();
    return s;
}

// ---------------- final LN + fused skip-LN chain (+ rolling cc zero) --------
__global__ void lnfinal_kernel(int li, int nstages, const float* __restrict__ ffw1,
                               const float* __restrict__ ang, const float* __restrict__ anb,
                               const float* __restrict__ sg, const float* __restrict__ sb) {
    __shared__ float part[8];
    int tid = threadIdx.x;
    int b = blockIdx.x;
    int rl = tid >> 6;
    int j = blockIdx.y * 4 + rl;
    int c = tid & 63;
    int warp = tid >> 5, lane = tid & 31;
    if (li < LNUM - 1) {
        int lb = blockIdx.y * BSZ + b;
        int zidx = lb * 256 + tid;
        if (zidx < BSZ * 9 * 64) zero_cc_slices(zidx);
    }
    const float* cst = g_constsL[li];
    float s = g_sL[1][li][b] + cst[3];
    float t = s * (s > 0.f ? cst[4] : cst[5]);
    int idx = (b * 64 + j) * 64 + c;
    float v = t * ffw1[j * 64 + c] + g_d0[idx];
    {
        float mean = rowsum64(v, part, warp, lane, rl) * (1.f / 64.f);
        float d = v - mean;
        float var = rowsum64(d * d, part, warp, lane, rl) * (1.f / 64.f);
        v = d * rsqrtf(var + 1e-3f) * ang[c] + anb[c];
    }
    g_bypass[li][idx] = v;
    float cur = v;
    for (int st = 0; st < nstages; st++) {
        int bidx = li - (1 << st) + 1;
        float u = (bidx == li) ? v : g_bypass[bidx][idx];
        float w = u + cur;
        float mean = rowsum64(w, part, warp, lane, rl) * (1.f / 64.f);
        float d = w - mean;
        float var = rowsum64(d * d, part, warp, lane, rl) * (1.f / 64.f);
        cur = d * rsqrtf(var + 1e-3f) * sg[st * 64 + c] + sb[st * 64 + c];
    }
    g_last[idx] = cur;
}

// ---------------- GRU: one block per (batch, dir), xg prefetch --------------
__global__ void __launch_bounds__(192) gru_kernel(const float* __restrict__ gru_r,
                                                  const float* __restrict__ gru_b, int li) {
    int b = blockIdx.x, dir = blockIdx.y;
    int g = threadIdx.x;
    float rcol[64];
    const float* rp = gru_r + (li * 2 + dir) * 12288;
#pragma unroll
    for (int j = 0; j < 64; j++) rcol[j] = rp[j * 192 + g];
    float br = gru_b[((li * 2 + dir) * 2 + 1) * 192 + g];
    __shared__ float hsh[64];
    __shared__ float hgsh[192];
    __shared__ float xgsh[192];
    if (g < 64) hsh[g] = g_mstate[b * 1024 + (li * 2 + dir) * 64 + g];
    __syncthreads();
    float* outp = dir ? g_back : g_fore;
    const float* xgbase = &g_xg[b * 64 * 384 + dir * 192 + g];
    float xgv_next = xgbase[(dir ? 63 : 0) * 384];
    for (int t = 0; t < 64; t++) {
        float xgv = xgv_next;
        if (t < 63) {
            int trow_n = dir ? (62 - t) : (t + 1);
            xgv_next = xgbase[trow_n * 384];
        }
        float a0 = 0.f, a1 = 0.f, a2 = 0.f, a3 = 0.f;
#pragma unroll
        for (int j = 0; j < 64; j += 4) {
            a0 += hsh[j]     * rcol[j];
            a1 += hsh[j + 1] * rcol[j + 1];
            a2 += hsh[j + 2] * rcol[j + 2];
            a3 += hsh[j + 3] * rcol[j + 3];
        }
        hgsh[g] = br + ((a0 + a1) + (a2 + a3));
        xgsh[g] = xgv;
        __syncthreads();
        if (g < 64) {
            float z = 1.f / (1.f + __expf(-(xgsh[g] + hgsh[g])));
            float rt = 1.f / (1.f + __expf(-(xgsh[64 + g] + hgsh[64 + g])));
            float cgate = tanhf(xgsh[128 + g] + rt * hgsh[128 + g]);
            float hn = z * hsh[g] + (1.f - z) * cgate;
            hsh[g] = hn;
            outp[(b * 64 + t) * 64 + g] = hn;
        }
        __syncthreads();
    }
    if (g < 64) g_states[((li * BSZ + b) * 2 + dir) * 64 + g] = hsh[g];
}

// ---------------- assemble outputs ----------------
__global__ void assemble_kernel(float* __restrict__ out) {
    int idx = blockIdx.x * 256 + threadIdx.x;
    const int N1 = BSZ * 5120;
    if (idx < N1) {
        int b = idx / 5120;
        int r = idx % 5120;
        int j = r / 80, c = r % 80;
        float v;
        if (c < 64) v = g_last[b * 4096 + j * 64 + c];
        else {
            int m = c - 64;
            int l = m >> 1, dir = m & 1;
            v = g_states[((l * BSZ + b) * 2 + dir) * 64 + j];
        }
        out[idx] = v;
    } else if (idx < N1 + BSZ * 1024) {
        int idx2 = idx - N1;
        int b = idx2 >> 10;
        int m = (idx2 >> 6) & 15;
        int t = idx2 & 63;
        int l = m >> 1, dir = m & 1;
        out[idx] = g_states[((l * BSZ + b) * 2 + dir) * 64 + t];
    }
}

// ---------------- host ----------------
extern "C" void kernel_launch(void* const* d_in, const int* in_sizes, int n_in,
                              void* d_out, int out_size) {
    const float* x       = (const float*)d_in[0];
    const float* state   = (const float*)d_in[1];
    const float* conv_w4 = (const float*)d_in[2];
    const float* conv_w3 = (const float*)d_in[3];
    const float* conv_w2 = (const float*)d_in[4];
    const float* conv_w1 = (const float*)d_in[5];
    const float* conv_b  = (const float*)d_in[6];
    const float* qkv_w   = (const float*)d_in[7];
    const float* qkv_b   = (const float*)d_in[8];
    const float* out_w   = (const float*)d_in[9];
    const float* out_b   = (const float*)d_in[10];
    const float* ff_w    = (const float*)d_in[11];
    const float* an_g    = (const float*)d_in[12];
    const float* an_b    = (const float*)d_in[13];
    const float* gru_k   = (const float*)d_in[14];
    const float* gru_r   = (const float*)d_in[15];
    const float* gru_b   = (const float*)d_in[16];
    const float* skip_g  = (const float*)d_in[17];
    const float* skip_b  = (const float*)d_in[18];
    float* out = (float*)d_out;

    prep0_kernel<<<4096, 256>>>(x, state);
    prep_all_kernel<<<dim3(8, 3), 256>>>(qkv_w, qkv_b, out_w, out_b, ff_w, gru_k, gru_b);

    for (int i = 0; i < LNUM; i++) {
        conv_kernel<<<dim3(75, 4), 256>>>(conv_w4 + i * 262144, conv_w3 + i * 110592,
                                          conv_w2 + i * 32768, conv_w1 + i * 4096,
                                          conv_b + i * 256);
        proj_kernel<<<dim3(400, 3), 256>>>(0, 0, i, nullptr, nullptr, nullptr);
        attn_kernel<<<dim3(BSZ, 8), 128>>>(0, 100, i);
        proj_kernel<<<dim3(256, 6), 256>>>(2, 0, i,
                                           ff_w + (i * 2 + 0) * 8192 + 4096,
                                           an_g + (i * 2 + 0) * 64,
                                           an_b + (i * 2 + 0) * 64);
        gru_kernel<<<dim3(BSZ, 2), 192>>>(gru_r, gru_b, i);
        proj_kernel<<<dim3(512, 3), 256>>>(1, 1, i, nullptr, nullptr, nullptr);
        attn_kernel<<<dim3(BSZ, 8), 128>>>(1, 128, i);
        int nst = 1;
        { int jj = 2; while ((i + 1) % jj == 0 && nst < 4) { nst++; jj *= 2; } }
        lnfinal_kernel<<<dim3(BSZ, 16), 256>>>(i, nst, ff_w + (i * 2 + 1) * 8192 + 4096,
                                               an_g + (i * 2 + 1) * 64, an_b + (i * 2 + 1) * 64,
                                               skip_g + i * 4 * 64, skip_b + i * 4 * 64);
    }
    assemble_kernel<<<6144, 256>>>(out);
}